// round 14
// baseline (speedup 1.0000x reference)
#include <cuda_runtime.h>
#include <cuda_bf16.h>
#include <math.h>

// ---------------- problem constants ----------------
#define BATCH   4096
#define SEQ     128
#define TSTEPS  32
#define PKTS    4
#define LEN_V   1500
#define IPD_V   256
#define EMB     64      // LEN_E == IPD_E == EV == 64
#define CAT     128
#define G3H     768     // 3*H
#define HID     256
#define LABELS  100

typedef unsigned long long ull;

// ---------------- device scratch (static, no allocs) ----------------
__device__ __align__(16) float g_LE[LEN_V * EMB];          // len_emb @ fc_w[:, :64]^T
__device__ __align__(16) float g_IE[IPD_V * EMB];          // ipd_emb @ fc_w[:, 64:]^T
__device__ __align__(16) float g_bias[G3H];                // b_ih + fold(fc_b)
__device__ __align__(16) float g_whhT[HID * G3H];          // w_hh transposed [k][g]
__device__ __align__(16) float g_LenTab[LEN_V * PKTS * G3H]; // [v][p][g]  18.4MB
__device__ __align__(16) float g_IpdTab[IPD_V * PKTS * G3H]; // [v][p][g]   3.1MB

// ---------------- f32x2 packed helpers (Blackwell) ----------------
__device__ __forceinline__ ull fma_f32x2(ull a, ull b, ull c) {
    ull d;
    asm("fma.rn.f32x2 %0, %1, %2, %3;" : "=l"(d) : "l"(a), "l"(b), "l"(c));
    return d;
}
__device__ __forceinline__ ull add_f32x2(ull a, ull b) {
    ull d;
    asm("add.rn.f32x2 %0, %1, %2;" : "=l"(d) : "l"(a), "l"(b));
    return d;
}
__device__ __forceinline__ ull pack_f32x2(float lo, float hi) {
    ull d;
    asm("mov.b64 %0, {%1, %2};" : "=l"(d) : "f"(lo), "f"(hi));
    return d;
}
__device__ __forceinline__ float2 unpack_f32x2(ull v) {
    float2 r;
    asm("mov.b64 {%0, %1}, %2;" : "=f"(r.x), "=f"(r.y) : "l"(v));
    return r;
}

// ---------------- K1: small prep (LE, IE, w_hh^T, fused bias) ----------------
__global__ void prep_kernel(const float* __restrict__ len_emb,
                            const float* __restrict__ ipd_emb,
                            const float* __restrict__ fc_w,
                            const float* __restrict__ fc_b,
                            const float* __restrict__ w_ih,
                            const float* __restrict__ w_hh,
                            const float* __restrict__ b_ih) {
    const int N_LE = LEN_V * EMB;          // 96000
    const int N_IE = IPD_V * EMB;          // 16384
    const int N_WT = HID * G3H;            // 196608
    const int N_B  = G3H;                  // 768
    const int TOTAL = N_LE + N_IE + N_WT + N_B;  // 309760 = 605*512
    int stride = gridDim.x * blockDim.x;
    for (int i = blockIdx.x * blockDim.x + threadIdx.x; i < TOTAL; i += stride) {
        if (i < N_LE) {
            int v = i >> 6, e = i & 63;
            const float4* a = reinterpret_cast<const float4*>(len_emb + v * 64);
            const float4* w = reinterpret_cast<const float4*>(fc_w + e * CAT);
            float acc = 0.f;
            #pragma unroll
            for (int c = 0; c < 16; ++c) {
                float4 av = a[c], wv = w[c];
                acc += av.x * wv.x + av.y * wv.y + av.z * wv.z + av.w * wv.w;
            }
            g_LE[i] = acc;
        } else if (i < N_LE + N_IE) {
            int j = i - N_LE;
            int v = j >> 6, e = j & 63;
            const float4* a = reinterpret_cast<const float4*>(ipd_emb + v * 64);
            const float4* w = reinterpret_cast<const float4*>(fc_w + e * CAT + 64);
            float acc = 0.f;
            #pragma unroll
            for (int c = 0; c < 16; ++c) {
                float4 av = a[c], wv = w[c];
                acc += av.x * wv.x + av.y * wv.y + av.z * wv.z + av.w * wv.w;
            }
            g_IE[j] = acc;
        } else if (i < N_LE + N_IE + N_WT) {
            int j = i - N_LE - N_IE;            // j = g*HID + k : coalesced read
            int g = j >> 8, k = j & 255;
            g_whhT[k * G3H + g] = w_hh[j];
        } else {
            int g = i - N_LE - N_IE - N_WT;
            float acc = b_ih[g];
            #pragma unroll 4
            for (int k = 0; k < HID; ++k) acc += fc_b[k & 63] * w_ih[g * HID + k];
            g_bias[g] = acc;
        }
    }
}

// ---------------- K2: build gather tables  Tab[v][p][g] = LE[v,:] . w_ih[g, p*64:+64] ----------------
#define VB 16
__global__ void table_kernel(const float* __restrict__ w_ih) {
    __shared__ float sE[VB * EMB];
    const int NLB = (LEN_V + VB - 1) / VB;     // 94
    bool is_ipd = (blockIdx.x >= NLB);
    int v0   = is_ipd ? (blockIdx.x - NLB) * VB : blockIdx.x * VB;
    int vmax = is_ipd ? IPD_V : LEN_V;
    const float* E = is_ipd ? g_IE : g_LE;
    float* Tab     = is_ipd ? g_IpdTab : g_LenTab;
    int tid = threadIdx.x;  // 256 threads
    for (int i = tid; i < VB * EMB; i += 256) {
        int v = v0 + (i >> 6);
        sE[i] = (v < vmax) ? E[v * EMB + (i & 63)] : 0.f;
    }
    __syncthreads();
    for (int pg = tid; pg < PKTS * G3H; pg += 256) {
        int p = pg / G3H, g = pg % G3H;
        float w[64];
        const float4* wr = reinterpret_cast<const float4*>(w_ih + g * HID + p * 64);
        #pragma unroll
        for (int q = 0; q < 16; ++q) {
            float4 t = wr[q];
            w[q * 4] = t.x; w[q * 4 + 1] = t.y; w[q * 4 + 2] = t.z; w[q * 4 + 3] = t.w;
        }
        for (int v = 0; v < VB; ++v) {
            if (v0 + v >= vmax) break;
            float acc = 0.f;
            #pragma unroll
            for (int e = 0; e < 64; ++e) acc += sE[v * 64 + e] * w[e];
            Tab[((v0 + v) * PKTS + p) * G3H + g] = acc;
        }
    }
}

// ---------------- K3: persistent GRU + head ----------------
// 128 CTAs x 512 threads; CTA owns 32 batch rows, h kept in SMEM across 32 steps.
// Thread (tx in [0,128), ty in [0,4)) owns hidden units u=2tx,2tx+1 (one f32x2
// per gate) for 8 rows m = ty + 4j. Halves per-k weight bytes vs the 4-col tile
// (24B/k instead of 48B/k) so L1 has 2x headroom under the FMA2 issue floor.
__global__ void __launch_bounds__(512, 1)
gru_kernel(const int* __restrict__ len_x, const int* __restrict__ ipd_x,
           const float* __restrict__ b_hh,
           const float* __restrict__ out_w, const float* __restrict__ out_b,
           float* __restrict__ out) {
    __shared__ __align__(16) float sh[32 * HID];   // 32KB: h[m][k]
    const int tid = threadIdx.x;
    const int tx = tid & 127;
    const int ty = tid >> 7;
    const int b0 = blockIdx.x * 32;
    const int u  = tx * 2;

    // zero h
    for (int i = tid; i < 32 * HID; i += 512) sh[i] = 0.f;

    // per-thread packed gate biases (r,z merged with b_hh; n kept split)
    const ull bRp = pack_f32x2(g_bias[u]       + b_hh[u],       g_bias[u + 1]       + b_hh[u + 1]);
    const ull bZp = pack_f32x2(g_bias[256 + u] + b_hh[256 + u], g_bias[256 + u + 1] + b_hh[256 + u + 1]);
    const ull bIp = pack_f32x2(g_bias[512 + u],                 g_bias[512 + u + 1]);
    const ull bHp = pack_f32x2(b_hh[512 + u],                   b_hh[512 + u + 1]);
    __syncthreads();

    const ull* W  = reinterpret_cast<const ull*>(g_whhT);    // [k][384] ull
    const ull* LT = reinterpret_cast<const ull*>(g_LenTab);
    const ull* IT = reinterpret_cast<const ull*>(g_IpdTab);

    for (int t = 0; t < TSTEPS; ++t) {
        ull aR[8], aZ[8], aNi[8], aNh[8];
        #pragma unroll
        for (int j = 0; j < 8; ++j) { aR[j] = bRp; aZ[j] = bZp; aNi[j] = bIp; aNh[j] = bHp; }

        // ---- gi gather from tables (LDG.64, coalesced over tx) ----
        #pragma unroll
        for (int j = 0; j < 8; ++j) {
            const int m = ty + 4 * j;
            const int rowoff = (b0 + m) * SEQ + t * 4;
            const int4 vl4 = *reinterpret_cast<const int4*>(len_x + rowoff);
            const int4 vi4 = *reinterpret_cast<const int4*>(ipd_x + rowoff);
            const int vls[4] = {vl4.x, vl4.y, vl4.z, vl4.w};
            const int vis[4] = {vi4.x, vi4.y, vi4.z, vi4.w};
            #pragma unroll
            for (int p = 0; p < 4; ++p) {
                const ull* Lp = LT + (size_t)(vls[p] * PKTS + p) * 384;
                const ull* Ip = IT + (size_t)(vis[p] * PKTS + p) * 384;
                aR[j]  = add_f32x2(add_f32x2(aR[j],  Lp[tx]),       Ip[tx]);
                aZ[j]  = add_f32x2(add_f32x2(aZ[j],  Lp[128 + tx]), Ip[128 + tx]);
                aNi[j] = add_f32x2(add_f32x2(aNi[j], Lp[256 + tx]), Ip[256 + tx]);
            }
        }

        // ---- gh = h @ w_hh^T  (packed f32x2 FMAs; 24B weights / 24 FMA2 per k) ----
        #pragma unroll 2
        for (int k = 0; k < HID; ++k) {
            const ull w0 = W[k * 384 + tx];          // r pair
            const ull w1 = W[k * 384 + 128 + tx];    // z pair
            const ull w2 = W[k * 384 + 256 + tx];    // n pair
            #pragma unroll
            for (int j = 0; j < 8; ++j) {
                const float hk = sh[(ty + 4 * j) * HID + k];
                const ull h2 = pack_f32x2(hk, hk);
                aR[j]  = fma_f32x2(h2, w0, aR[j]);
                aZ[j]  = fma_f32x2(h2, w1, aZ[j]);
                aNh[j] = fma_f32x2(h2, w2, aNh[j]);
            }
        }

        // ---- gates + h update ----
        float2 hn[8];
        #pragma unroll
        for (int j = 0; j < 8; ++j) {
            const int m = ty + 4 * j;
            const float2 hold = *reinterpret_cast<const float2*>(&sh[m * HID + u]);
            const float2 rv = unpack_f32x2(aR[j]);
            const float2 zv = unpack_f32x2(aZ[j]);
            const float2 iv = unpack_f32x2(aNi[j]);
            const float2 nv = unpack_f32x2(aNh[j]);
            const float r0 = 1.f / (1.f + expf(-rv.x));
            const float r1 = 1.f / (1.f + expf(-rv.y));
            const float z0 = 1.f / (1.f + expf(-zv.x));
            const float z1 = 1.f / (1.f + expf(-zv.y));
            const float n0 = tanhf(iv.x + r0 * nv.x);
            const float n1 = tanhf(iv.y + r1 * nv.y);
            hn[j].x = (1.f - z0) * n0 + z0 * hold.x;
            hn[j].y = (1.f - z1) * n1 + z1 * hold.y;
        }
        __syncthreads();
        #pragma unroll
        for (int j = 0; j < 8; ++j) {
            const int m = ty + 4 * j;
            *reinterpret_cast<float2*>(&sh[m * HID + u]) = hn[j];
        }
        __syncthreads();
    }

    // ---- head: logits = h @ out_w^T + out_b ----
    for (int i = tid; i < 32 * LABELS; i += 512) {
        const int m = i / LABELS, l = i % LABELS;
        float acc = out_b[l];
        const float* hw = sh + m * HID;
        const float* ww = out_w + l * HID;
        #pragma unroll 8
        for (int k = 0; k < HID; ++k) acc += hw[k] * ww[k];
        out[(b0 + m) * LABELS + l] = acc;
    }
}

// ---------------- launch ----------------
extern "C" void kernel_launch(void* const* d_in, const int* in_sizes, int n_in,
                              void* d_out, int out_size) {
    const int*   len_x   = (const int*)d_in[0];
    const int*   ipd_x   = (const int*)d_in[1];
    const float* len_emb = (const float*)d_in[2];
    const float* ipd_emb = (const float*)d_in[3];
    const float* fc_w    = (const float*)d_in[4];
    const float* fc_b    = (const float*)d_in[5];
    const float* w_ih    = (const float*)d_in[6];
    const float* w_hh    = (const float*)d_in[7];
    const float* b_ih    = (const float*)d_in[8];
    const float* b_hh    = (const float*)d_in[9];
    const float* out_w   = (const float*)d_in[10];
    const float* out_b   = (const float*)d_in[11];
    float* out = (float*)d_out;

    prep_kernel<<<605, 512>>>(len_emb, ipd_emb, fc_w, fc_b, w_ih, w_hh, b_ih);
    const int nlb = (LEN_V + VB - 1) / VB;           // 94
    const int nib = (IPD_V + VB - 1) / VB;           // 16
    table_kernel<<<nlb + nib, 256>>>(w_ih);
    gru_kernel<<<BATCH / 32, 512>>>(len_x, ipd_x, b_hh, out_w, out_b, out);
}

// round 15
// speedup vs baseline: 1.0036x; 1.0036x over previous
#include <cuda_runtime.h>
#include <cuda_bf16.h>
#include <math.h>

// ---------------- problem constants ----------------
#define BATCH   4096
#define SEQ     128
#define TSTEPS  32
#define PKTS    4
#define LEN_V   1500
#define IPD_V   256
#define EMB     64      // LEN_E == IPD_E == EV == 64
#define CAT     128
#define G3H     768     // 3*H
#define HID     256
#define LABELS  100

typedef unsigned long long ull;

// ---------------- device scratch (static, no allocs) ----------------
__device__ __align__(16) float g_LE[LEN_V * EMB];          // len_emb @ fc_w[:, :64]^T
__device__ __align__(16) float g_IE[IPD_V * EMB];          // ipd_emb @ fc_w[:, 64:]^T
__device__ __align__(16) float g_bias[G3H];                // b_ih + fold(fc_b)
__device__ __align__(16) float g_whhT[HID * G3H];          // w_hh transposed [k][g]
__device__ __align__(16) float g_LenTab[LEN_V * PKTS * G3H]; // [v][p][g]  18.4MB
__device__ __align__(16) float g_IpdTab[IPD_V * PKTS * G3H]; // [v][p][g]   3.1MB

// ---------------- f32x2 packed helpers (Blackwell) ----------------
__device__ __forceinline__ ull fma_f32x2(ull a, ull b, ull c) {
    ull d;
    asm("fma.rn.f32x2 %0, %1, %2, %3;" : "=l"(d) : "l"(a), "l"(b), "l"(c));
    return d;
}
__device__ __forceinline__ ull add_f32x2(ull a, ull b) {
    ull d;
    asm("add.rn.f32x2 %0, %1, %2;" : "=l"(d) : "l"(a), "l"(b));
    return d;
}
__device__ __forceinline__ ull pack_f32x2(float lo, float hi) {
    ull d;
    asm("mov.b64 %0, {%1, %2};" : "=l"(d) : "f"(lo), "f"(hi));
    return d;
}
__device__ __forceinline__ float2 unpack_f32x2(ull v) {
    float2 r;
    asm("mov.b64 {%0, %1}, %2;" : "=f"(r.x), "=f"(r.y) : "l"(v));
    return r;
}

// ---------------- K1: small prep (LE, IE, w_hh^T, fused bias) ----------------
__global__ void prep_kernel(const float* __restrict__ len_emb,
                            const float* __restrict__ ipd_emb,
                            const float* __restrict__ fc_w,
                            const float* __restrict__ fc_b,
                            const float* __restrict__ w_ih,
                            const float* __restrict__ w_hh,
                            const float* __restrict__ b_ih) {
    const int N_LE = LEN_V * EMB;          // 96000
    const int N_IE = IPD_V * EMB;          // 16384
    const int N_WT = HID * G3H;            // 196608
    const int N_B  = G3H;                  // 768
    const int TOTAL = N_LE + N_IE + N_WT + N_B;  // 309760 = 605*512
    int stride = gridDim.x * blockDim.x;
    for (int i = blockIdx.x * blockDim.x + threadIdx.x; i < TOTAL; i += stride) {
        if (i < N_LE) {
            int v = i >> 6, e = i & 63;
            const float4* a = reinterpret_cast<const float4*>(len_emb + v * 64);
            const float4* w = reinterpret_cast<const float4*>(fc_w + e * CAT);
            float acc = 0.f;
            #pragma unroll
            for (int c = 0; c < 16; ++c) {
                float4 av = a[c], wv = w[c];
                acc += av.x * wv.x + av.y * wv.y + av.z * wv.z + av.w * wv.w;
            }
            g_LE[i] = acc;
        } else if (i < N_LE + N_IE) {
            int j = i - N_LE;
            int v = j >> 6, e = j & 63;
            const float4* a = reinterpret_cast<const float4*>(ipd_emb + v * 64);
            const float4* w = reinterpret_cast<const float4*>(fc_w + e * CAT + 64);
            float acc = 0.f;
            #pragma unroll
            for (int c = 0; c < 16; ++c) {
                float4 av = a[c], wv = w[c];
                acc += av.x * wv.x + av.y * wv.y + av.z * wv.z + av.w * wv.w;
            }
            g_IE[j] = acc;
        } else if (i < N_LE + N_IE + N_WT) {
            int j = i - N_LE - N_IE;            // j = g*HID + k : coalesced read
            int g = j >> 8, k = j & 255;
            g_whhT[k * G3H + g] = w_hh[j];
        } else {
            int g = i - N_LE - N_IE - N_WT;
            float acc = b_ih[g];
            #pragma unroll 4
            for (int k = 0; k < HID; ++k) acc += fc_b[k & 63] * w_ih[g * HID + k];
            g_bias[g] = acc;
        }
    }
}

// ---------------- K2: build gather tables  Tab[v][p][g] = LE[v,:] . w_ih[g, p*64:+64] ----------------
#define VB 16
__global__ void table_kernel(const float* __restrict__ w_ih) {
    __shared__ float sE[VB * EMB];
    const int NLB = (LEN_V + VB - 1) / VB;     // 94
    bool is_ipd = (blockIdx.x >= NLB);
    int v0   = is_ipd ? (blockIdx.x - NLB) * VB : blockIdx.x * VB;
    int vmax = is_ipd ? IPD_V : LEN_V;
    const float* E = is_ipd ? g_IE : g_LE;
    float* Tab     = is_ipd ? g_IpdTab : g_LenTab;
    int tid = threadIdx.x;  // 256 threads
    for (int i = tid; i < VB * EMB; i += 256) {
        int v = v0 + (i >> 6);
        sE[i] = (v < vmax) ? E[v * EMB + (i & 63)] : 0.f;
    }
    __syncthreads();
    for (int pg = tid; pg < PKTS * G3H; pg += 256) {
        int p = pg / G3H, g = pg % G3H;
        float w[64];
        const float4* wr = reinterpret_cast<const float4*>(w_ih + g * HID + p * 64);
        #pragma unroll
        for (int q = 0; q < 16; ++q) {
            float4 t = wr[q];
            w[q * 4] = t.x; w[q * 4 + 1] = t.y; w[q * 4 + 2] = t.z; w[q * 4 + 3] = t.w;
        }
        for (int v = 0; v < VB; ++v) {
            if (v0 + v >= vmax) break;
            float acc = 0.f;
            #pragma unroll
            for (int e = 0; e < 64; ++e) acc += sE[v * 64 + e] * w[e];
            Tab[((v0 + v) * PKTS + p) * G3H + g] = acc;
        }
    }
}

// ---------------- K3: persistent GRU + head ----------------
// 128 CTAs x 512 threads; CTA owns 32 batch rows, h kept in SMEM across 32 steps.
// Thread (tx in [0,128), ty in [0,4)) owns hidden units u=2tx,2tx+1 (one f32x2
// per gate) for 8 rows m = ty + 4j. Halves per-k weight bytes vs the 4-col tile
// (24B/k instead of 48B/k) so L1 has 2x headroom under the FMA2 issue floor.
__global__ void __launch_bounds__(512, 1)
gru_kernel(const int* __restrict__ len_x, const int* __restrict__ ipd_x,
           const float* __restrict__ b_hh,
           const float* __restrict__ out_w, const float* __restrict__ out_b,
           float* __restrict__ out) {
    __shared__ __align__(16) float sh[32 * HID];   // 32KB: h[m][k]
    const int tid = threadIdx.x;
    const int tx = tid & 127;
    const int ty = tid >> 7;
    const int b0 = blockIdx.x * 32;
    const int u  = tx * 2;

    // zero h
    for (int i = tid; i < 32 * HID; i += 512) sh[i] = 0.f;

    // per-thread packed gate biases (r,z merged with b_hh; n kept split)
    const ull bRp = pack_f32x2(g_bias[u]       + b_hh[u],       g_bias[u + 1]       + b_hh[u + 1]);
    const ull bZp = pack_f32x2(g_bias[256 + u] + b_hh[256 + u], g_bias[256 + u + 1] + b_hh[256 + u + 1]);
    const ull bIp = pack_f32x2(g_bias[512 + u],                 g_bias[512 + u + 1]);
    const ull bHp = pack_f32x2(b_hh[512 + u],                   b_hh[512 + u + 1]);
    __syncthreads();

    const ull* W  = reinterpret_cast<const ull*>(g_whhT);    // [k][384] ull
    const ull* LT = reinterpret_cast<const ull*>(g_LenTab);
    const ull* IT = reinterpret_cast<const ull*>(g_IpdTab);

    for (int t = 0; t < TSTEPS; ++t) {
        ull aR[8], aZ[8], aNi[8], aNh[8];
        #pragma unroll
        for (int j = 0; j < 8; ++j) { aR[j] = bRp; aZ[j] = bZp; aNi[j] = bIp; aNh[j] = bHp; }

        // ---- gi gather from tables (LDG.64, coalesced over tx) ----
        #pragma unroll
        for (int j = 0; j < 8; ++j) {
            const int m = ty + 4 * j;
            const int rowoff = (b0 + m) * SEQ + t * 4;
            const int4 vl4 = *reinterpret_cast<const int4*>(len_x + rowoff);
            const int4 vi4 = *reinterpret_cast<const int4*>(ipd_x + rowoff);
            const int vls[4] = {vl4.x, vl4.y, vl4.z, vl4.w};
            const int vis[4] = {vi4.x, vi4.y, vi4.z, vi4.w};
            #pragma unroll
            for (int p = 0; p < 4; ++p) {
                const ull* Lp = LT + (size_t)(vls[p] * PKTS + p) * 384;
                const ull* Ip = IT + (size_t)(vis[p] * PKTS + p) * 384;
                aR[j]  = add_f32x2(add_f32x2(aR[j],  Lp[tx]),       Ip[tx]);
                aZ[j]  = add_f32x2(add_f32x2(aZ[j],  Lp[128 + tx]), Ip[128 + tx]);
                aNi[j] = add_f32x2(add_f32x2(aNi[j], Lp[256 + tx]), Ip[256 + tx]);
            }
        }

        // ---- gh = h @ w_hh^T  (packed f32x2 FMAs; 24B weights / 24 FMA2 per k) ----
        #pragma unroll 2
        for (int k = 0; k < HID; ++k) {
            const ull w0 = W[k * 384 + tx];          // r pair
            const ull w1 = W[k * 384 + 128 + tx];    // z pair
            const ull w2 = W[k * 384 + 256 + tx];    // n pair
            #pragma unroll
            for (int j = 0; j < 8; ++j) {
                const float hk = sh[(ty + 4 * j) * HID + k];
                const ull h2 = pack_f32x2(hk, hk);
                aR[j]  = fma_f32x2(h2, w0, aR[j]);
                aZ[j]  = fma_f32x2(h2, w1, aZ[j]);
                aNh[j] = fma_f32x2(h2, w2, aNh[j]);
            }
        }

        // ---- gates + h update ----
        float2 hn[8];
        #pragma unroll
        for (int j = 0; j < 8; ++j) {
            const int m = ty + 4 * j;
            const float2 hold = *reinterpret_cast<const float2*>(&sh[m * HID + u]);
            const float2 rv = unpack_f32x2(aR[j]);
            const float2 zv = unpack_f32x2(aZ[j]);
            const float2 iv = unpack_f32x2(aNi[j]);
            const float2 nv = unpack_f32x2(aNh[j]);
            const float r0 = 1.f / (1.f + expf(-rv.x));
            const float r1 = 1.f / (1.f + expf(-rv.y));
            const float z0 = 1.f / (1.f + expf(-zv.x));
            const float z1 = 1.f / (1.f + expf(-zv.y));
            const float n0 = tanhf(iv.x + r0 * nv.x);
            const float n1 = tanhf(iv.y + r1 * nv.y);
            hn[j].x = (1.f - z0) * n0 + z0 * hold.x;
            hn[j].y = (1.f - z1) * n1 + z1 * hold.y;
        }
        __syncthreads();
        #pragma unroll
        for (int j = 0; j < 8; ++j) {
            const int m = ty + 4 * j;
            *reinterpret_cast<float2*>(&sh[m * HID + u]) = hn[j];
        }
        __syncthreads();
    }

    // ---- head: logits = h @ out_w^T + out_b ----
    for (int i = tid; i < 32 * LABELS; i += 512) {
        const int m = i / LABELS, l = i % LABELS;
        float acc = out_b[l];
        const float* hw = sh + m * HID;
        const float* ww = out_w + l * HID;
        #pragma unroll 8
        for (int k = 0; k < HID; ++k) acc += hw[k] * ww[k];
        out[(b0 + m) * LABELS + l] = acc;
    }
}

// ---------------- launch ----------------
extern "C" void kernel_launch(void* const* d_in, const int* in_sizes, int n_in,
                              void* d_out, int out_size) {
    const int*   len_x   = (const int*)d_in[0];
    const int*   ipd_x   = (const int*)d_in[1];
    const float* len_emb = (const float*)d_in[2];
    const float* ipd_emb = (const float*)d_in[3];
    const float* fc_w    = (const float*)d_in[4];
    const float* fc_b    = (const float*)d_in[5];
    const float* w_ih    = (const float*)d_in[6];
    const float* w_hh    = (const float*)d_in[7];
    const float* b_ih    = (const float*)d_in[8];
    const float* b_hh    = (const float*)d_in[9];
    const float* out_w   = (const float*)d_in[10];
    const float* out_b   = (const float*)d_in[11];
    float* out = (float*)d_out;

    prep_kernel<<<605, 512>>>(len_emb, ipd_emb, fc_w, fc_b, w_ih, w_hh, b_ih);
    const int nlb = (LEN_V + VB - 1) / VB;           // 94
    const int nib = (IPD_V + VB - 1) / VB;           // 16
    table_kernel<<<nlb + nib, 256>>>(w_ih);
    gru_kernel<<<BATCH / 32, 512>>>(len_x, ipd_x, b_hh, out_w, out_b, out);
}